// round 1
// baseline (speedup 1.0000x reference)
#include <cuda_runtime.h>
#include <cstddef>

// Problem constants
#define B_DIM   16384
#define C_DIM   1024
#define HD_DIM  1024   // H*D
#define O_DIM   1024
#define LN_EPS  1e-5f

// Scratch (allocation-free: __device__ globals)
__device__ float g_M[(size_t)O_DIM * C_DIM];            // 4 MB:  M = W_fc @ W_V
__device__ float g_Z[2ull * B_DIM * O_DIM];             // 128 MB: z1 rows [0,B), z2 rows [B,2B)

// ---------------------------------------------------------------------------
// GEMM NT: C[i,j] = sum_k A[i,k] * B[j,k]
// A: Md x Kd row-major (K contiguous), B: Nd x Kd row-major (K contiguous)
// Tile 128x128x16, 256 threads, 8x8 per thread (split 4+4 for vectorized LDS)
// ---------------------------------------------------------------------------
__global__ __launch_bounds__(256, 2)
void gemm_nt_kernel(const float* __restrict__ A, const float* __restrict__ B,
                    float* __restrict__ C, int Md, int Nd, int Kd)
{
    __shared__ float As[16][128];
    __shared__ float Bs[16][128];

    const int tid = threadIdx.x;
    const int tx = tid & 15;          // 0..15  (N direction)
    const int ty = tid >> 4;          // 0..15  (M direction)
    const int bm = blockIdx.y * 128;
    const int bn = blockIdx.x * 128;

    float acc[8][8];
    #pragma unroll
    for (int i = 0; i < 8; i++)
        #pragma unroll
        for (int j = 0; j < 8; j++)
            acc[i][j] = 0.f;

    // Load mapping: each thread loads 2 float4 of A and 2 float4 of B per k-tile
    const int loadRow = tid >> 2;            // 0..63
    const int loadK   = (tid & 3) << 2;      // 0,4,8,12

    const float* Aptr = A + (size_t)(bm + loadRow) * Kd + loadK;
    const float* Bptr = B + (size_t)(bn + loadRow) * Kd + loadK;

    for (int k0 = 0; k0 < Kd; k0 += 16) {
        #pragma unroll
        for (int s = 0; s < 2; s++) {
            const float4 av = *reinterpret_cast<const float4*>(Aptr + (size_t)s * 64 * Kd + k0);
            const float4 bv = *reinterpret_cast<const float4*>(Bptr + (size_t)s * 64 * Kd + k0);
            const int r = loadRow + s * 64;
            As[loadK + 0][r] = av.x; As[loadK + 1][r] = av.y;
            As[loadK + 2][r] = av.z; As[loadK + 3][r] = av.w;
            Bs[loadK + 0][r] = bv.x; Bs[loadK + 1][r] = bv.y;
            Bs[loadK + 2][r] = bv.z; Bs[loadK + 3][r] = bv.w;
        }
        __syncthreads();

        #pragma unroll
        for (int kk = 0; kk < 16; kk++) {
            float a[8], b[8];
            *reinterpret_cast<float4*>(&a[0]) = *reinterpret_cast<const float4*>(&As[kk][ty * 4]);
            *reinterpret_cast<float4*>(&a[4]) = *reinterpret_cast<const float4*>(&As[kk][64 + ty * 4]);
            *reinterpret_cast<float4*>(&b[0]) = *reinterpret_cast<const float4*>(&Bs[kk][tx * 4]);
            *reinterpret_cast<float4*>(&b[4]) = *reinterpret_cast<const float4*>(&Bs[kk][64 + tx * 4]);
            #pragma unroll
            for (int i = 0; i < 8; i++)
                #pragma unroll
                for (int j = 0; j < 8; j++)
                    acc[i][j] = fmaf(a[i], b[j], acc[i][j]);
        }
        __syncthreads();
    }

    #pragma unroll
    for (int i = 0; i < 8; i++) {
        const int r = bm + ((i < 4) ? (ty * 4 + i) : (64 + ty * 4 + i - 4));
        float4 v0 = make_float4(acc[i][0], acc[i][1], acc[i][2], acc[i][3]);
        float4 v1 = make_float4(acc[i][4], acc[i][5], acc[i][6], acc[i][7]);
        *reinterpret_cast<float4*>(&C[(size_t)r * Nd + bn + tx * 4])      = v0;
        *reinterpret_cast<float4*>(&C[(size_t)r * Nd + bn + 64 + tx * 4]) = v1;
    }
}

// ---------------------------------------------------------------------------
// GEMM NN: C[i,j] = sum_k A[i,k] * B[k,j]
// A: Md x Kd row-major, B: Kd x Nd row-major (N contiguous)
// Tile 64x64x16, 256 threads, 4x4 per thread. Used for M = W_fc @ W_V.
// ---------------------------------------------------------------------------
__global__ __launch_bounds__(256, 4)
void gemm_nn_kernel(const float* __restrict__ A, const float* __restrict__ B,
                    float* __restrict__ C, int Md, int Nd, int Kd)
{
    __shared__ float As[16][64];
    __shared__ float Bs[16][64];

    const int tid = threadIdx.x;
    const int tx = tid & 15;          // 0..15 (N)
    const int ty = tid >> 4;          // 0..15 (M)
    const int bm = blockIdx.y * 64;
    const int bn = blockIdx.x * 64;

    float acc[4][4];
    #pragma unroll
    for (int i = 0; i < 4; i++)
        #pragma unroll
        for (int j = 0; j < 4; j++)
            acc[i][j] = 0.f;

    const int aRow = tid >> 2;            // 0..63
    const int aK   = (tid & 3) << 2;      // 0,4,8,12
    const int bK   = tid >> 4;            // 0..15
    const int bJ   = (tid & 15) << 2;     // 0..60

    for (int k0 = 0; k0 < Kd; k0 += 16) {
        const float4 av = *reinterpret_cast<const float4*>(
            A + (size_t)(bm + aRow) * Kd + k0 + aK);
        As[aK + 0][aRow] = av.x; As[aK + 1][aRow] = av.y;
        As[aK + 2][aRow] = av.z; As[aK + 3][aRow] = av.w;

        *reinterpret_cast<float4*>(&Bs[bK][bJ]) = *reinterpret_cast<const float4*>(
            B + (size_t)(k0 + bK) * Nd + bn + bJ);
        __syncthreads();

        #pragma unroll
        for (int kk = 0; kk < 16; kk++) {
            float a[4], b[4];
            *reinterpret_cast<float4*>(&a[0]) = *reinterpret_cast<const float4*>(&As[kk][ty * 4]);
            *reinterpret_cast<float4*>(&b[0]) = *reinterpret_cast<const float4*>(&Bs[kk][tx * 4]);
            #pragma unroll
            for (int i = 0; i < 4; i++)
                #pragma unroll
                for (int j = 0; j < 4; j++)
                    acc[i][j] = fmaf(a[i], b[j], acc[i][j]);
        }
        __syncthreads();
    }

    #pragma unroll
    for (int i = 0; i < 4; i++) {
        float4 v = make_float4(acc[i][0], acc[i][1], acc[i][2], acc[i][3]);
        *reinterpret_cast<float4*>(&C[(size_t)(bm + ty * 4 + i) * Nd + bn + tx * 4]) = v;
    }
}

// ---------------------------------------------------------------------------
// LN epilogue: out[b,:] = LN(z1[b,:])*gamma + beta + LN(z2[b,:])*gamma + beta
// One block (256 threads) per batch row; each thread handles 4 elements of
// each of z1, z2 (strided for coalescing).
// ---------------------------------------------------------------------------
__global__ __launch_bounds__(256)
void ln_add_kernel(const float* __restrict__ Z,
                   const float* __restrict__ gamma,
                   const float* __restrict__ beta,
                   float* __restrict__ out)
{
    const int b = blockIdx.x;
    const int t = threadIdx.x;
    const float* z1 = Z + (size_t)b * O_DIM;
    const float* z2 = Z + (size_t)(B_DIM + b) * O_DIM;

    float v1[4], v2[4];
    float s1 = 0.f, q1 = 0.f, s2 = 0.f, q2 = 0.f;
    #pragma unroll
    for (int i = 0; i < 4; i++) {
        const int o = t + i * 256;
        v1[i] = z1[o];
        v2[i] = z2[o];
        s1 += v1[i]; q1 += v1[i] * v1[i];
        s2 += v2[i]; q2 += v2[i] * v2[i];
    }

    // warp reduce
    #pragma unroll
    for (int o = 16; o > 0; o >>= 1) {
        s1 += __shfl_xor_sync(0xffffffffu, s1, o);
        q1 += __shfl_xor_sync(0xffffffffu, q1, o);
        s2 += __shfl_xor_sync(0xffffffffu, s2, o);
        q2 += __shfl_xor_sync(0xffffffffu, q2, o);
    }
    __shared__ float red[4][8];
    const int w = t >> 5, l = t & 31;
    if (l == 0) { red[0][w] = s1; red[1][w] = q1; red[2][w] = s2; red[3][w] = q2; }
    __syncthreads();
    float S1 = 0.f, Q1 = 0.f, S2 = 0.f, Q2 = 0.f;
    #pragma unroll
    for (int i = 0; i < 8; i++) {
        S1 += red[0][i]; Q1 += red[1][i]; S2 += red[2][i]; Q2 += red[3][i];
    }

    const float inv = 1.0f / (float)O_DIM;
    const float mu1 = S1 * inv;
    const float mu2 = S2 * inv;
    const float r1 = rsqrtf(Q1 * inv - mu1 * mu1 + LN_EPS);
    const float r2 = rsqrtf(Q2 * inv - mu2 * mu2 + LN_EPS);

    #pragma unroll
    for (int i = 0; i < 4; i++) {
        const int o = t + i * 256;
        const float g = gamma[o];
        const float bt = beta[o];
        out[(size_t)b * O_DIM + o] =
            ((v1[i] - mu1) * r1 + (v2[i] - mu2) * r2) * g + 2.0f * bt;
    }
}

// ---------------------------------------------------------------------------
// Launch: seqlen==1 => attention == V, so the whole network collapses to
//   M = W_fc @ W_V ;  out = LN(x1 @ M^T) + LN(x2 @ M^T)  (with gamma/beta)
// ---------------------------------------------------------------------------
extern "C" void kernel_launch(void* const* d_in, const int* in_sizes, int n_in,
                              void* d_out, int out_size)
{
    const float* x1    = (const float*)d_in[0];
    const float* x2    = (const float*)d_in[1];
    // d_in[2] = W_Q, d_in[3] = W_K  -- dead code (softmax over seqlen 1 == 1)
    const float* W_V   = (const float*)d_in[4];
    const float* W_fc  = (const float*)d_in[5];
    const float* gamma = (const float*)d_in[6];
    const float* beta  = (const float*)d_in[7];
    float* out = (float*)d_out;

    float* dM = nullptr;
    float* dZ = nullptr;
    cudaGetSymbolAddress((void**)&dM, g_M);
    cudaGetSymbolAddress((void**)&dZ, g_Z);

    // 1) M[o,c] = sum_e W_fc[o,e] * W_V[e,c]   (NN gemm, 1024^3)
    {
        dim3 grid(C_DIM / 64, O_DIM / 64);
        gemm_nn_kernel<<<grid, 256>>>(W_fc, W_V, dM, O_DIM, C_DIM, HD_DIM);
    }

    // 2) z1 = x1 @ M^T, z2 = x2 @ M^T   (NT gemms, 16384 x 1024 x 1024 each)
    {
        dim3 grid(O_DIM / 128, B_DIM / 128);
        gemm_nt_kernel<<<grid, 256>>>(x1, dM, dZ, B_DIM, O_DIM, C_DIM);
        gemm_nt_kernel<<<grid, 256>>>(x2, dM, dZ + (size_t)B_DIM * O_DIM, B_DIM, O_DIM, C_DIM);
    }

    // 3) out = LN(z1)*g + b + LN(z2)*g + b
    ln_add_kernel<<<B_DIM, 256>>>(dZ, gamma, beta, out);
}

// round 4
// speedup vs baseline: 1.8887x; 1.8887x over previous
#include <cuda_runtime.h>
#include <cuda_bf16.h>
#include <cstdint>
#include <cstddef>

#define B_DIM   16384
#define C_DIM   1024   // K of main GEMM
#define O_DIM   1024   // N of main GEMM
#define LN_EPS  1e-5f

// ---------------- scratch (device globals: allocation-free) ----------------
__device__ float          g_M  [(size_t)O_DIM * C_DIM];          // 4 MB fp32 M = W_fc @ W_V
__device__ float          g_Z  [2ull * B_DIM * O_DIM];           // 128 MB z1|z2
__device__ __nv_bfloat16  g_Xhi[2ull * B_DIM * C_DIM];           // 64 MB
__device__ __nv_bfloat16  g_Xlo[2ull * B_DIM * C_DIM];           // 64 MB
__device__ __nv_bfloat16  g_Mhi[(size_t)O_DIM * C_DIM];          // 2 MB
__device__ __nv_bfloat16  g_Mlo[(size_t)O_DIM * C_DIM];          // 2 MB

// ---------------- PTX helpers ----------------
__device__ __forceinline__ uint32_t cvta_smem(const void* p) {
    uint32_t r;
    asm("{.reg .u64 t; cvta.to.shared.u64 t, %1; cvt.u32.u64 %0, t;}" : "=r"(r) : "l"(p));
    return r;
}
__device__ __forceinline__ void cp_async16(uint32_t smem, const void* g) {
    asm volatile("cp.async.cg.shared.global [%0], [%1], 16;\n" :: "r"(smem), "l"(g));
}
__device__ __forceinline__ void ldm_x4(uint32_t* r, uint32_t addr) {
    asm volatile("ldmatrix.sync.aligned.m8n8.x4.shared.b16 {%0,%1,%2,%3}, [%4];\n"
        : "=r"(r[0]), "=r"(r[1]), "=r"(r[2]), "=r"(r[3]) : "r"(addr));
}
__device__ __forceinline__ void mma16816(float* d, const uint32_t* a, const uint32_t* b) {
    asm volatile("mma.sync.aligned.m16n8k16.row.col.f32.bf16.bf16.f32 "
        "{%0,%1,%2,%3},{%4,%5,%6,%7},{%8,%9},{%0,%1,%2,%3};\n"
        : "+f"(d[0]), "+f"(d[1]), "+f"(d[2]), "+f"(d[3])
        : "r"(a[0]), "r"(a[1]), "r"(a[2]), "r"(a[3]), "r"(b[0]), "r"(b[1]));
}

// ---------------------------------------------------------------------------
// Decompose fp32 -> (hi, lo) bf16 planes. 4 elems / thread.
// ---------------------------------------------------------------------------
__global__ __launch_bounds__(256)
void decompose_kernel(const float* __restrict__ src,
                      __nv_bfloat16* __restrict__ hi,
                      __nv_bfloat16* __restrict__ lo)
{
    const size_t i = (size_t)blockIdx.x * 256 + threadIdx.x;
    float4 v = reinterpret_cast<const float4*>(src)[i];
    float f[4] = {v.x, v.y, v.z, v.w};
    __nv_bfloat16 hb[4], lb[4];
#pragma unroll
    for (int j = 0; j < 4; j++) {
        __nv_bfloat16 h = __float2bfloat16(f[j]);
        hb[j] = h;
        lb[j] = __float2bfloat16(f[j] - __bfloat162float(h));
    }
    reinterpret_cast<uint2*>(hi)[i] = *reinterpret_cast<uint2*>(hb);
    reinterpret_cast<uint2*>(lo)[i] = *reinterpret_cast<uint2*>(lb);
}

// ---------------------------------------------------------------------------
// Small fp32 NN GEMM for M = W_fc @ W_V (1024^3).
// ---------------------------------------------------------------------------
__global__ __launch_bounds__(256, 4)
void gemm_nn_kernel(const float* __restrict__ A, const float* __restrict__ B,
                    float* __restrict__ C, int Md, int Nd, int Kd)
{
    __shared__ float As[16][64];
    __shared__ float Bs[16][64];

    const int tid = threadIdx.x;
    const int tx = tid & 15;
    const int ty = tid >> 4;
    const int bm = blockIdx.y * 64;
    const int bn = blockIdx.x * 64;

    float acc[4][4];
#pragma unroll
    for (int i = 0; i < 4; i++)
#pragma unroll
        for (int j = 0; j < 4; j++) acc[i][j] = 0.f;

    const int aRow = tid >> 2;
    const int aK   = (tid & 3) << 2;
    const int bK   = tid >> 4;
    const int bJ   = (tid & 15) << 2;

    for (int k0 = 0; k0 < Kd; k0 += 16) {
        const float4 av = *reinterpret_cast<const float4*>(A + (size_t)(bm + aRow) * Kd + k0 + aK);
        As[aK + 0][aRow] = av.x; As[aK + 1][aRow] = av.y;
        As[aK + 2][aRow] = av.z; As[aK + 3][aRow] = av.w;
        *reinterpret_cast<float4*>(&Bs[bK][bJ]) =
            *reinterpret_cast<const float4*>(B + (size_t)(k0 + bK) * Nd + bn + bJ);
        __syncthreads();
#pragma unroll
        for (int kk = 0; kk < 16; kk++) {
            float a[4], b[4];
            *reinterpret_cast<float4*>(&a[0]) = *reinterpret_cast<const float4*>(&As[kk][ty * 4]);
            *reinterpret_cast<float4*>(&b[0]) = *reinterpret_cast<const float4*>(&Bs[kk][tx * 4]);
#pragma unroll
            for (int i = 0; i < 4; i++)
#pragma unroll
                for (int j = 0; j < 4; j++) acc[i][j] = fmaf(a[i], b[j], acc[i][j]);
        }
        __syncthreads();
    }
#pragma unroll
    for (int i = 0; i < 4; i++) {
        float4 v = make_float4(acc[i][0], acc[i][1], acc[i][2], acc[i][3]);
        *reinterpret_cast<float4*>(&C[(size_t)(bm + ty * 4 + i) * Nd + bn + tx * 4]) = v;
    }
}

// ---------------------------------------------------------------------------
// Main GEMM (NT): Z[i,j] = sum_k X[i,k] * M[j,k], fp32-accurate via bf16 3-MMA
// (Ah*Bh + Ah*Bl + Al*Bh). CTA 128x128, 8 warps (4Mx2N, warp tile 32x64),
// K-chunk 16, cp.async double-buffer. STATIC smem only (48KB, no opt-in):
// rows padded to 48B -> 16B-aligned, conflict-free for ldmatrix.
// ---------------------------------------------------------------------------
#define KC       16
#define SROW     48              // bytes per smem row (32B data + 16B pad)
#define PLANE_B  (128 * SROW)    // 6144 B per plane
#define STAGE_B  (4 * PLANE_B)   // 24576 B per stage (Ah|Al|Bh|Bl)
#define K_ITERS  (C_DIM / KC)    // 64

__global__ __launch_bounds__(256)
void gemm_bf16x3_kernel(const __nv_bfloat16* __restrict__ Xhi,
                        const __nv_bfloat16* __restrict__ Xlo,
                        const __nv_bfloat16* __restrict__ Mhi,
                        const __nv_bfloat16* __restrict__ Mlo,
                        float* __restrict__ Z)
{
    __shared__ __align__(16) char smem[2 * STAGE_B];   // 49152 B static
    const uint32_t smem_u32 = cvta_smem(smem);

    const int tid    = threadIdx.x;
    const int warp   = tid >> 5;
    const int lane   = tid & 31;
    const int warp_m = warp >> 1;       // 0..3
    const int warp_n = warp & 1;        // 0..1
    const int bm = blockIdx.y * 128;
    const int bn = blockIdx.x * 128;
    const size_t xoff = (size_t)blockIdx.z * ((size_t)B_DIM * C_DIM);
    const size_t zoff = (size_t)blockIdx.z * ((size_t)B_DIM * O_DIM);

    // per-plane global bases for the cp.async stage loader
    const __nv_bfloat16* base[4];
    base[0] = Xhi + xoff + (size_t)bm * C_DIM;
    base[1] = Xlo + xoff + (size_t)bm * C_DIM;
    base[2] = Mhi + (size_t)bn * C_DIM;
    base[3] = Mlo + (size_t)bn * C_DIM;

    float acc[2][8][4];
#pragma unroll
    for (int m = 0; m < 2; m++)
#pragma unroll
        for (int n = 0; n < 8; n++)
#pragma unroll
            for (int q = 0; q < 4; q++) acc[m][n][q] = 0.f;

    // lane-resident ldmatrix offsets (bytes, within a plane)
    uint32_t aoff[2], boff[4];
    {
        const int ra = (lane & 7) + 8 * ((lane >> 3) & 1);
        const int ka = (lane >> 4) * 16;                  // k-half in bytes
        aoff[0] = (uint32_t)((warp_m * 32 + 0  + ra) * SROW + ka);
        aoff[1] = (uint32_t)((warp_m * 32 + 16 + ra) * SROW + ka);
        const int rb = (lane & 7) + 8 * (lane >> 4);
        const int kb = ((lane >> 3) & 1) * 16;
#pragma unroll
        for (int p = 0; p < 4; p++)
            boff[p] = (uint32_t)((warp_n * 64 + 16 * p + rb) * SROW + kb);
    }

    auto issue_stage = [&](int buf, int k0) {
        const uint32_t sb = smem_u32 + buf * STAGE_B;
#pragma unroll
        for (int pl = 0; pl < 4; pl++) {        // tid<256: each pl is one plane
            const int slot = tid;               // 256 slots = 128 rows x 2 chunks
            const int c    = slot & 1;          // 16B chunk within 32B row
            const int row  = slot >> 1;         // 0..127
            cp_async16(sb + pl * PLANE_B + row * SROW + c * 16,
                       base[pl] + (size_t)row * C_DIM + k0 + c * 8);
        }
        asm volatile("cp.async.commit_group;\n" ::);
    };

    auto compute_stage = [&](int buf) {
        const uint32_t sb = smem_u32 + buf * STAGE_B;
        uint32_t ah[2][4], al[2][4];
#pragma unroll
        for (int m = 0; m < 2; m++) {
            ldm_x4(ah[m], sb + aoff[m]);
            ldm_x4(al[m], sb + PLANE_B + aoff[m]);
        }
#pragma unroll
        for (int p = 0; p < 4; p++) {           // 4 n16 groups -> n-blocks 2p, 2p+1
            uint32_t bh[4], bl[4];
            ldm_x4(bh, sb + 2 * PLANE_B + boff[p]);
            ldm_x4(bl, sb + 3 * PLANE_B + boff[p]);
#pragma unroll
            for (int j = 0; j < 2; j++) {
                const uint32_t* bhp = &bh[j * 2];
                const uint32_t* blp = &bl[j * 2];
#pragma unroll
                for (int m = 0; m < 2; m++) {
                    mma16816(acc[m][2 * p + j], ah[m], bhp);
                    mma16816(acc[m][2 * p + j], ah[m], blp);
                    mma16816(acc[m][2 * p + j], al[m], bhp);
                }
            }
        }
    };

    // prologue
    issue_stage(0, 0);

    // steady state: prefetch next while computing current
#pragma unroll 1
    for (int it = 0; it < K_ITERS - 1; it++) {
        issue_stage((it + 1) & 1, (it + 1) * KC);
        asm volatile("cp.async.wait_group 1;\n" ::);
        __syncthreads();
        compute_stage(it & 1);
        __syncthreads();
    }
    // drain
    asm volatile("cp.async.wait_group 0;\n" ::);
    __syncthreads();
    compute_stage((K_ITERS - 1) & 1);

    // epilogue: fp32 stores to Z
    const int qr = lane >> 2;
    const int qc = (lane & 3) * 2;
#pragma unroll
    for (int m = 0; m < 2; m++) {
        const int row0 = bm + warp_m * 32 + m * 16 + qr;
#pragma unroll
        for (int n = 0; n < 8; n++) {
            const int col = bn + warp_n * 64 + n * 8 + qc;
            *reinterpret_cast<float2*>(&Z[zoff + (size_t)row0 * 1024 + col]) =
                make_float2(acc[m][n][0], acc[m][n][1]);
            *reinterpret_cast<float2*>(&Z[zoff + (size_t)(row0 + 8) * 1024 + col]) =
                make_float2(acc[m][n][2], acc[m][n][3]);
        }
    }
}

// ---------------------------------------------------------------------------
// LN epilogue: out = LN(z1)*g + b + LN(z2)*g + b
// ---------------------------------------------------------------------------
__global__ __launch_bounds__(256)
void ln_add_kernel(const float* __restrict__ Z,
                   const float* __restrict__ gamma,
                   const float* __restrict__ beta,
                   float* __restrict__ out)
{
    const int b = blockIdx.x;
    const int t = threadIdx.x;
    const float* z1 = Z + (size_t)b * O_DIM;
    const float* z2 = Z + (size_t)(B_DIM + b) * O_DIM;

    float v1[4], v2[4];
    float s1 = 0.f, q1 = 0.f, s2 = 0.f, q2 = 0.f;
#pragma unroll
    for (int i = 0; i < 4; i++) {
        const int o = t + i * 256;
        v1[i] = z1[o];
        v2[i] = z2[o];
        s1 += v1[i]; q1 += v1[i] * v1[i];
        s2 += v2[i]; q2 += v2[i] * v2[i];
    }
#pragma unroll
    for (int o = 16; o > 0; o >>= 1) {
        s1 += __shfl_xor_sync(0xffffffffu, s1, o);
        q1 += __shfl_xor_sync(0xffffffffu, q1, o);
        s2 += __shfl_xor_sync(0xffffffffu, s2, o);
        q2 += __shfl_xor_sync(0xffffffffu, q2, o);
    }
    __shared__ float red[4][8];
    const int w = t >> 5, l = t & 31;
    if (l == 0) { red[0][w] = s1; red[1][w] = q1; red[2][w] = s2; red[3][w] = q2; }
    __syncthreads();
    float S1 = 0.f, Q1 = 0.f, S2 = 0.f, Q2 = 0.f;
#pragma unroll
    for (int i = 0; i < 8; i++) { S1 += red[0][i]; Q1 += red[1][i]; S2 += red[2][i]; Q2 += red[3][i]; }

    const float inv = 1.0f / (float)O_DIM;
    const float mu1 = S1 * inv;
    const float mu2 = S2 * inv;
    const float r1 = rsqrtf(Q1 * inv - mu1 * mu1 + LN_EPS);
    const float r2 = rsqrtf(Q2 * inv - mu2 * mu2 + LN_EPS);
#pragma unroll
    for (int i = 0; i < 4; i++) {
        const int o = t + i * 256;
        out[(size_t)b * O_DIM + o] =
            ((v1[i] - mu1) * r1 + (v2[i] - mu2) * r2) * gamma[o] + 2.0f * beta[o];
    }
}

// ---------------------------------------------------------------------------
// seqlen==1 => softmax over a single score == 1 => attention == V.
// Whole net collapses to: M = W_fc@W_V ; out = LN(x1@M^T) + LN(x2@M^T).
// ---------------------------------------------------------------------------
extern "C" void kernel_launch(void* const* d_in, const int* in_sizes, int n_in,
                              void* d_out, int out_size)
{
    const float* x1    = (const float*)d_in[0];
    const float* x2    = (const float*)d_in[1];
    const float* W_V   = (const float*)d_in[4];
    const float* W_fc  = (const float*)d_in[5];
    const float* gamma = (const float*)d_in[6];
    const float* beta  = (const float*)d_in[7];
    float* out = (float*)d_out;

    float *dM, *dZ;
    __nv_bfloat16 *dXhi, *dXlo, *dMhi, *dMlo;
    cudaGetSymbolAddress((void**)&dM,   g_M);
    cudaGetSymbolAddress((void**)&dZ,   g_Z);
    cudaGetSymbolAddress((void**)&dXhi, g_Xhi);
    cudaGetSymbolAddress((void**)&dXlo, g_Xlo);
    cudaGetSymbolAddress((void**)&dMhi, g_Mhi);
    cudaGetSymbolAddress((void**)&dMlo, g_Mlo);

    // 1) M = W_fc @ W_V (fp32)
    gemm_nn_kernel<<<dim3(C_DIM / 64, O_DIM / 64), 256>>>(W_fc, W_V, dM, O_DIM, C_DIM, C_DIM);

    // 2) decompose M, x1, x2 into bf16 hi/lo planes
    decompose_kernel<<<(O_DIM * C_DIM) / 1024, 256>>>(dM, dMhi, dMlo);
    decompose_kernel<<<((size_t)B_DIM * C_DIM) / 1024, 256>>>(x1, dXhi, dXlo);
    decompose_kernel<<<((size_t)B_DIM * C_DIM) / 1024, 256>>>(x2, dXhi + (size_t)B_DIM * C_DIM,
                                                              dXlo + (size_t)B_DIM * C_DIM);

    // 3) z1/z2 = x @ M^T via bf16 3-MMA tensor-core GEMM (fused over blockIdx.z)
    gemm_bf16x3_kernel<<<dim3(O_DIM / 128, B_DIM / 128, 2), 256>>>(
        dXhi, dXlo, dMhi, dMlo, dZ);

    // 4) out = LN(z1)*g + b + LN(z2)*g + b
    ln_add_kernel<<<B_DIM, 256>>>(dZ, gamma, beta, out);
}

// round 6
// speedup vs baseline: 1.8930x; 1.0023x over previous
#include <cuda_runtime.h>
#include <cuda_bf16.h>
#include <cstdint>
#include <cstddef>

#define B_DIM   16384
#define C_DIM   1024   // K of main GEMM
#define O_DIM   1024   // N of main GEMM
#define LN_EPS  1e-5f

// ---------------- scratch (device globals: allocation-free) ----------------
__device__ float          g_M  [(size_t)O_DIM * C_DIM];          // 4 MB fp32 M = W_fc @ W_V
__device__ float          g_Z  [2ull * B_DIM * O_DIM];           // 128 MB z1|z2
__device__ __nv_bfloat16  g_Xhi[2ull * B_DIM * C_DIM];           // 64 MB
__device__ __nv_bfloat16  g_Xlo[2ull * B_DIM * C_DIM];           // 64 MB
__device__ __nv_bfloat16  g_Mhi[(size_t)O_DIM * C_DIM];          // 2 MB
__device__ __nv_bfloat16  g_Mlo[(size_t)O_DIM * C_DIM];          // 2 MB

// ---------------- PTX helpers ----------------
__device__ __forceinline__ uint32_t cvta_smem(const void* p) {
    uint32_t r;
    asm("{.reg .u64 t; cvta.to.shared.u64 t, %1; cvt.u32.u64 %0, t;}" : "=r"(r) : "l"(p));
    return r;
}
__device__ __forceinline__ void cp_async16(uint32_t smem, const void* g) {
    asm volatile("cp.async.cg.shared.global [%0], [%1], 16;\n" :: "r"(smem), "l"(g));
}
__device__ __forceinline__ void ldm_x4(uint32_t* r, uint32_t addr) {
    asm volatile("ldmatrix.sync.aligned.m8n8.x4.shared.b16 {%0,%1,%2,%3}, [%4];\n"
        : "=r"(r[0]), "=r"(r[1]), "=r"(r[2]), "=r"(r[3]) : "r"(addr));
}
__device__ __forceinline__ void mma16816(float* d, const uint32_t* a, const uint32_t* b) {
    asm volatile("mma.sync.aligned.m16n8k16.row.col.f32.bf16.bf16.f32 "
        "{%0,%1,%2,%3},{%4,%5,%6,%7},{%8,%9},{%0,%1,%2,%3};\n"
        : "+f"(d[0]), "+f"(d[1]), "+f"(d[2]), "+f"(d[3])
        : "r"(a[0]), "r"(a[1]), "r"(a[2]), "r"(a[3]), "r"(b[0]), "r"(b[1]));
}

// ---------------------------------------------------------------------------
// Decompose fp32 -> (hi, lo) bf16 planes. 4 elems / thread.
// ---------------------------------------------------------------------------
__global__ __launch_bounds__(256)
void decompose_kernel(const float* __restrict__ src,
                      __nv_bfloat16* __restrict__ hi,
                      __nv_bfloat16* __restrict__ lo)
{
    const size_t i = (size_t)blockIdx.x * 256 + threadIdx.x;
    float4 v = reinterpret_cast<const float4*>(src)[i];
    float f[4] = {v.x, v.y, v.z, v.w};
    __nv_bfloat16 hb[4], lb[4];
#pragma unroll
    for (int j = 0; j < 4; j++) {
        __nv_bfloat16 h = __float2bfloat16(f[j]);
        hb[j] = h;
        lb[j] = __float2bfloat16(f[j] - __bfloat162float(h));
    }
    reinterpret_cast<uint2*>(hi)[i] = *reinterpret_cast<uint2*>(hb);
    reinterpret_cast<uint2*>(lo)[i] = *reinterpret_cast<uint2*>(lb);
}

// ---------------------------------------------------------------------------
// Small fp32 NN GEMM for M = W_fc @ W_V (1024^3).
// ---------------------------------------------------------------------------
__global__ __launch_bounds__(256, 4)
void gemm_nn_kernel(const float* __restrict__ A, const float* __restrict__ B,
                    float* __restrict__ C, int Md, int Nd, int Kd)
{
    __shared__ float As[16][64];
    __shared__ float Bs[16][64];

    const int tid = threadIdx.x;
    const int tx = tid & 15;
    const int ty = tid >> 4;
    const int bm = blockIdx.y * 64;
    const int bn = blockIdx.x * 64;

    float acc[4][4];
#pragma unroll
    for (int i = 0; i < 4; i++)
#pragma unroll
        for (int j = 0; j < 4; j++) acc[i][j] = 0.f;

    const int aRow = tid >> 2;
    const int aK   = (tid & 3) << 2;
    const int bK   = tid >> 4;
    const int bJ   = (tid & 15) << 2;

    for (int k0 = 0; k0 < Kd; k0 += 16) {
        const float4 av = *reinterpret_cast<const float4*>(A + (size_t)(bm + aRow) * Kd + k0 + aK);
        As[aK + 0][aRow] = av.x; As[aK + 1][aRow] = av.y;
        As[aK + 2][aRow] = av.z; As[aK + 3][aRow] = av.w;
        *reinterpret_cast<float4*>(&Bs[bK][bJ]) =
            *reinterpret_cast<const float4*>(B + (size_t)(k0 + bK) * Nd + bn + bJ);
        __syncthreads();
#pragma unroll
        for (int kk = 0; kk < 16; kk++) {
            float a[4], b[4];
            *reinterpret_cast<float4*>(&a[0]) = *reinterpret_cast<const float4*>(&As[kk][ty * 4]);
            *reinterpret_cast<float4*>(&b[0]) = *reinterpret_cast<const float4*>(&Bs[kk][tx * 4]);
#pragma unroll
            for (int i = 0; i < 4; i++)
#pragma unroll
                for (int j = 0; j < 4; j++) acc[i][j] = fmaf(a[i], b[j], acc[i][j]);
        }
        __syncthreads();
    }
#pragma unroll
    for (int i = 0; i < 4; i++) {
        float4 v = make_float4(acc[i][0], acc[i][1], acc[i][2], acc[i][3]);
        *reinterpret_cast<float4*>(&C[(size_t)(bm + ty * 4 + i) * Nd + bn + tx * 4]) = v;
    }
}

// ---------------------------------------------------------------------------
// Main GEMM (NT): Z[i,j] = sum_k X[i,k] * M[j,k], fp32-accurate via bf16 3-MMA
// (Ah*Bh + Ah*Bl + Al*Bh). CTA 128x128, 8 warps (4Mx2N, warp tile 32x64),
// K-chunk 16, cp.async double-buffer, static 48KB smem.
// Per-n16-group B loads (R4 shape); term-major within group for ILP.
// ---------------------------------------------------------------------------
#define KC       16
#define SROW     48              // bytes per smem row (32B data + 16B pad)
#define PLANE_B  (128 * SROW)    // 6144 B per plane
#define STAGE_B  (4 * PLANE_B)   // 24576 B per stage (Ah|Al|Bh|Bl)
#define K_ITERS  (C_DIM / KC)    // 64

__global__ __launch_bounds__(256)
void gemm_bf16x3_kernel(const __nv_bfloat16* __restrict__ Xhi,
                        const __nv_bfloat16* __restrict__ Xlo,
                        const __nv_bfloat16* __restrict__ Mhi,
                        const __nv_bfloat16* __restrict__ Mlo,
                        float* __restrict__ Z)
{
    __shared__ __align__(16) char smem[2 * STAGE_B];   // 49152 B static
    const uint32_t smem_u32 = cvta_smem(smem);

    const int tid    = threadIdx.x;
    const int warp   = tid >> 5;
    const int lane   = tid & 31;
    const int warp_m = warp >> 1;       // 0..3
    const int warp_n = warp & 1;        // 0..1
    const int bm = blockIdx.y * 128;
    const int bn = blockIdx.x * 128;
    const size_t xoff = (size_t)blockIdx.z * ((size_t)B_DIM * C_DIM);
    const size_t zoff = (size_t)blockIdx.z * ((size_t)B_DIM * O_DIM);

    // per-plane global bases for the cp.async stage loader
    const __nv_bfloat16* base[4];
    base[0] = Xhi + xoff + (size_t)bm * C_DIM;
    base[1] = Xlo + xoff + (size_t)bm * C_DIM;
    base[2] = Mhi + (size_t)bn * C_DIM;
    base[3] = Mlo + (size_t)bn * C_DIM;

    float acc[2][8][4];
#pragma unroll
    for (int m = 0; m < 2; m++)
#pragma unroll
        for (int n = 0; n < 8; n++)
#pragma unroll
            for (int q = 0; q < 4; q++) acc[m][n][q] = 0.f;

    // lane-resident ldmatrix offsets (bytes, within a plane)
    uint32_t aoff[2], boff[4];
    {
        const int ra = (lane & 7) + 8 * ((lane >> 3) & 1);
        const int ka = (lane >> 4) * 16;                  // k-half in bytes
        aoff[0] = (uint32_t)((warp_m * 32 + 0  + ra) * SROW + ka);
        aoff[1] = (uint32_t)((warp_m * 32 + 16 + ra) * SROW + ka);
        const int rb = (lane & 7) + 8 * (lane >> 4);
        const int kb = ((lane >> 3) & 1) * 16;
#pragma unroll
        for (int p = 0; p < 4; p++)
            boff[p] = (uint32_t)((warp_n * 64 + 16 * p + rb) * SROW + kb);
    }

    auto issue_stage = [&](int buf, int k0) {
        const uint32_t sb = smem_u32 + buf * STAGE_B;
#pragma unroll
        for (int pl = 0; pl < 4; pl++) {        // tid<256: each pl is one plane
            const int c    = tid & 1;           // 16B chunk within 32B row
            const int row  = tid >> 1;          // 0..127
            cp_async16(sb + pl * PLANE_B + row * SROW + c * 16,
                       base[pl] + (size_t)row * C_DIM + k0 + c * 8);
        }
        asm volatile("cp.async.commit_group;\n" ::);
    };

    auto compute_stage = [&](int buf) {
        const uint32_t sb = smem_u32 + buf * STAGE_B;
        uint32_t ah[2][4], al[2][4];
#pragma unroll
        for (int m = 0; m < 2; m++) {
            ldm_x4(ah[m], sb + aoff[m]);
            ldm_x4(al[m], sb + PLANE_B + aoff[m]);
        }
#pragma unroll
        for (int p = 0; p < 4; p++) {           // 4 n16 groups -> n-blocks 2p, 2p+1
            uint32_t bh[4], bl[4];
            ldm_x4(bh, sb + 2 * PLANE_B + boff[p]);
            ldm_x4(bl, sb + 3 * PLANE_B + boff[p]);
            // term-major within the group: 4 independent MMAs per term
#pragma unroll
            for (int j = 0; j < 2; j++)
#pragma unroll
                for (int m = 0; m < 2; m++)
                    mma16816(acc[m][2 * p + j], ah[m], &bh[j * 2]);
#pragma unroll
            for (int j = 0; j < 2; j++)
#pragma unroll
                for (int m = 0; m < 2; m++)
                    mma16816(acc[m][2 * p + j], ah[m], &bl[j * 2]);
#pragma unroll
            for (int j = 0; j < 2; j++)
#pragma unroll
                for (int m = 0; m < 2; m++)
                    mma16816(acc[m][2 * p + j], al[m], &bh[j * 2]);
        }
    };

    // prologue
    issue_stage(0, 0);

    // steady state: prefetch next while computing current
#pragma unroll 1
    for (int it = 0; it < K_ITERS - 1; it++) {
        issue_stage((it + 1) & 1, (it + 1) * KC);
        asm volatile("cp.async.wait_group 1;\n" ::);
        __syncthreads();
        compute_stage(it & 1);
        __syncthreads();
    }
    // drain
    asm volatile("cp.async.wait_group 0;\n" ::);
    __syncthreads();
    compute_stage((K_ITERS - 1) & 1);

    // epilogue: fp32 stores to Z
    const int qr = lane >> 2;
    const int qc = (lane & 3) * 2;
#pragma unroll
    for (int m = 0; m < 2; m++) {
        const int row0 = bm + warp_m * 32 + m * 16 + qr;
#pragma unroll
        for (int n = 0; n < 8; n++) {
            const int col = bn + warp_n * 64 + n * 8 + qc;
            *reinterpret_cast<float2*>(&Z[zoff + (size_t)row0 * 1024 + col]) =
                make_float2(acc[m][n][0], acc[m][n][1]);
            *reinterpret_cast<float2*>(&Z[zoff + (size_t)(row0 + 8) * 1024 + col]) =
                make_float2(acc[m][n][2], acc[m][n][3]);
        }
    }
}

// ---------------------------------------------------------------------------
// LN epilogue: out = LN(z1)*g + b + LN(z2)*g + b
// ---------------------------------------------------------------------------
__global__ __launch_bounds__(256)
void ln_add_kernel(const float* __restrict__ Z,
                   const float* __restrict__ gamma,
                   const float* __restrict__ beta,
                   float* __restrict__ out)
{
    const int b = blockIdx.x;
    const int t = threadIdx.x;
    const float* z1 = Z + (size_t)b * O_DIM;
    const float* z2 = Z + (size_t)(B_DIM + b) * O_DIM;

    float v1[4], v2[4];
    float s1 = 0.f, q1 = 0.f, s2 = 0.f, q2 = 0.f;
#pragma unroll
    for (int i = 0; i < 4; i++) {
        const int o = t + i * 256;
        v1[i] = z1[o];
        v2[i] = z2[o];
        s1 += v1[i]; q1 += v1[i] * v1[i];
        s2 += v2[i]; q2 += v2[i] * v2[i];
    }
#pragma unroll
    for (int o = 16; o > 0; o >>= 1) {
        s1 += __shfl_xor_sync(0xffffffffu, s1, o);
        q1 += __shfl_xor_sync(0xffffffffu, q1, o);
        s2 += __shfl_xor_sync(0xffffffffu, s2, o);
        q2 += __shfl_xor_sync(0xffffffffu, q2, o);
    }
    __shared__ float red[4][8];
    const int w = t >> 5, l = t & 31;
    if (l == 0) { red[0][w] = s1; red[1][w] = q1; red[2][w] = s2; red[3][w] = q2; }
    __syncthreads();
    float S1 = 0.f, Q1 = 0.f, S2 = 0.f, Q2 = 0.f;
#pragma unroll
    for (int i = 0; i < 8; i++) { S1 += red[0][i]; Q1 += red[1][i]; S2 += red[2][i]; Q2 += red[3][i]; }

    const float inv = 1.0f / (float)O_DIM;
    const float mu1 = S1 * inv;
    const float mu2 = S2 * inv;
    const float r1 = rsqrtf(Q1 * inv - mu1 * mu1 + LN_EPS);
    const float r2 = rsqrtf(Q2 * inv - mu2 * mu2 + LN_EPS);
#pragma unroll
    for (int i = 0; i < 4; i++) {
        const int o = t + i * 256;
        out[(size_t)b * O_DIM + o] =
            ((v1[i] - mu1) * r1 + (v2[i] - mu2) * r2) * gamma[o] + 2.0f * beta[o];
    }
}

// ---------------------------------------------------------------------------
// seqlen==1 => softmax over a single score == 1 => attention == V.
// Whole net collapses to: M = W_fc@W_V ; out = LN(x1@M^T) + LN(x2@M^T).
// ---------------------------------------------------------------------------
extern "C" void kernel_launch(void* const* d_in, const int* in_sizes, int n_in,
                              void* d_out, int out_size)
{
    const float* x1    = (const float*)d_in[0];
    const float* x2    = (const float*)d_in[1];
    const float* W_V   = (const float*)d_in[4];
    const float* W_fc  = (const float*)d_in[5];
    const float* gamma = (const float*)d_in[6];
    const float* beta  = (const float*)d_in[7];
    float* out = (float*)d_out;

    float *dM, *dZ;
    __nv_bfloat16 *dXhi, *dXlo, *dMhi, *dMlo;
    cudaGetSymbolAddress((void**)&dM,   g_M);
    cudaGetSymbolAddress((void**)&dZ,   g_Z);
    cudaGetSymbolAddress((void**)&dXhi, g_Xhi);
    cudaGetSymbolAddress((void**)&dXlo, g_Xlo);
    cudaGetSymbolAddress((void**)&dMhi, g_Mhi);
    cudaGetSymbolAddress((void**)&dMlo, g_Mlo);

    // 1) M = W_fc @ W_V (fp32)
    gemm_nn_kernel<<<dim3(C_DIM / 64, O_DIM / 64), 256>>>(W_fc, W_V, dM, O_DIM, C_DIM, C_DIM);

    // 2) decompose M, x1, x2 into bf16 hi/lo planes
    decompose_kernel<<<(O_DIM * C_DIM) / 1024, 256>>>(dM, dMhi, dMlo);
    decompose_kernel<<<((size_t)B_DIM * C_DIM) / 1024, 256>>>(x1, dXhi, dXlo);
    decompose_kernel<<<((size_t)B_DIM * C_DIM) / 1024, 256>>>(x2, dXhi + (size_t)B_DIM * C_DIM,
                                                              dXlo + (size_t)B_DIM * C_DIM);

    // 3) z1/z2 = x @ M^T via bf16 3-MMA tensor-core GEMM (fused over blockIdx.z)
    gemm_bf16x3_kernel<<<dim3(O_DIM / 128, B_DIM / 128, 2), 256>>>(
        dXhi, dXlo, dMhi, dMlo, dZ);

    // 4) out = LN(z1)*g + b + LN(z2)*g + b
    ln_add_kernel<<<B_DIM, 256>>>(dZ, gamma, beta, out);
}